// round 1
// baseline (speedup 1.0000x reference)
#include <cuda_runtime.h>
#include <cstdint>

// Problem dims (fixed by the dataset)
#define BATCH 32
#define F_IN  512
#define T_LEN 256
#define HID   1024
#define OUTD  128

#define N_CHAINS (BATCH * HID)             // 32768 LIF chains per layer
#define Z_ELEMS  ((size_t)BATCH * HID * T_LEN)  // 8388608

// Output layout (floats): spikes0, spikes1, readouts0, readouts1, voltages0, voltages1, counts[2]
#define SOFF0 ((size_t)0)
#define SOFF1 ((size_t)8388608)
#define ROFF0 ((size_t)16777216)
#define ROFF1 ((size_t)17825792)
#define VOFF0 ((size_t)18874368)
#define VOFF1 ((size_t)27262976)
#define CNTOFF ((size_t)35651584)

// Scratch: synaptic current z for the active layer (reused between layers)
__device__ float g_z[Z_ELEMS];
__device__ unsigned long long g_cnt[2];

__global__ void init_counts_kernel() {
    g_cnt[0] = 0ull;
    g_cnt[1] = 0ull;
}

// Y[b, m, n] = sum_k A[m,k] * X[b,k,n]
// A: [M,K] row-major (weight, shared across batch)
// X: [B,K,N] with n contiguous
// Y: [B,M,N] with n contiguous
template<int BM, int BN, int BK, int TM, int TN>
__global__ __launch_bounds__((BM/TM)*(BN/TN))
void gemm_bt_kernel(const float* __restrict__ A,
                    const float* __restrict__ X,
                    float* __restrict__ Y,
                    int M, int K, int N)
{
    constexpr int THREADS = (BM / TM) * (BN / TN);
    __shared__ float As[BK][BM];
    __shared__ float Bs[BK][BN];

    const int b  = blockIdx.z;
    const int m0 = blockIdx.y * BM;
    const int n0 = blockIdx.x * BN;
    const float* __restrict__ Xb = X + (size_t)b * K * N;
    float* __restrict__ Yb = Y + (size_t)b * M * N;

    const int tid  = threadIdx.x;
    const int tcol = tid % (BN / TN);   // along N
    const int trow = tid / (BN / TN);   // along M

    float acc[TM][TN];
#pragma unroll
    for (int i = 0; i < TM; i++)
#pragma unroll
        for (int j = 0; j < TN; j++)
            acc[i][j] = 0.0f;

    for (int k0 = 0; k0 < K; k0 += BK) {
        // Load A tile [BM x BK] -> As[k][m]
#pragma unroll
        for (int i = tid; i < BM * BK; i += THREADS) {
            int m = i / BK;
            int k = i % BK;
            As[k][m] = A[(size_t)(m0 + m) * K + (k0 + k)];
        }
        // Load X tile [BK x BN] -> Bs[k][n] (coalesced along n)
#pragma unroll
        for (int i = tid; i < BK * BN; i += THREADS) {
            int k = i / BN;
            int n = i % BN;
            Bs[k][n] = Xb[(size_t)(k0 + k) * N + (n0 + n)];
        }
        __syncthreads();

#pragma unroll
        for (int kk = 0; kk < BK; kk++) {
            float av[TM], bv[TN];
#pragma unroll
            for (int i = 0; i < TM; i++) av[i] = As[kk][trow * TM + i];
#pragma unroll
            for (int j = 0; j < TN; j++) bv[j] = Bs[kk][tcol * TN + j];
#pragma unroll
            for (int i = 0; i < TM; i++)
#pragma unroll
                for (int j = 0; j < TN; j++)
                    acc[i][j] += av[i] * bv[j];
        }
        __syncthreads();
    }

#pragma unroll
    for (int i = 0; i < TM; i++) {
        const size_t row = (size_t)(m0 + trow * TM + i) * N + n0 + tcol * TN;
#pragma unroll
        for (int j = 0; j < TN; j++)
            Yb[row + j] = acc[i][j];
    }
}

// CUBA LIF recurrence over trailing time axis. One thread per (b, h) chain.
// cur[t]  = 0.75 * cur[t-1] + z[t]
// volt[t] = 0.97 * volt[t-1] + cur[t]   (store pre-reset)
// spike   = volt >= 1.25 ; hard reset volt -> 0 on spike
__global__ __launch_bounds__(256)
void lif_kernel(float* __restrict__ v_out,
                float* __restrict__ s_out,
                int layer)
{
    const int idx = blockIdx.x * blockDim.x + threadIdx.x; // 0 .. N_CHAINS-1 (exact)
    const float* __restrict__ zp = g_z + (size_t)idx * T_LEN;
    float* __restrict__ vp = v_out + (size_t)idx * T_LEN;
    float* __restrict__ sp = s_out + (size_t)idx * T_LEN;

    float cur = 0.0f, volt = 0.0f;
    unsigned cnt = 0;

#pragma unroll 4
    for (int t = 0; t < T_LEN; t++) {
        cur  = 0.75f * cur + zp[t];
        volt = 0.97f * volt + cur;
        vp[t] = volt;
        const bool s = (volt >= 1.25f);
        sp[t] = s ? 1.0f : 0.0f;
        cnt += (unsigned)s;
        if (s) volt = 0.0f;
    }

    // Deterministic integer reduction: block-level, then one atomic per block.
    __shared__ unsigned red[256];
    red[threadIdx.x] = cnt;
    __syncthreads();
#pragma unroll
    for (int off = 128; off > 0; off >>= 1) {
        if (threadIdx.x < off) red[threadIdx.x] += red[threadIdx.x + off];
        __syncthreads();
    }
    if (threadIdx.x == 0)
        atomicAdd(&g_cnt[layer], (unsigned long long)red[0]);
}

__global__ void finalize_counts_kernel(float* __restrict__ out)
{
    const double total = (double)((size_t)BATCH * HID * T_LEN);
    out[0] = (float)((double)g_cnt[0] / total);
    out[1] = (float)((double)g_cnt[1] / total);
}

extern "C" void kernel_launch(void* const* d_in, const int* in_sizes, int n_in,
                              void* d_out, int out_size)
{
    const float* spike = (const float*)d_in[0]; // [32, 512, 256]
    const float* W1    = (const float*)d_in[1]; // [1024, 512]
    const float* W2    = (const float*)d_in[2]; // [1024, 1024]
    const float* R1    = (const float*)d_in[3]; // [128, 1024]
    const float* R2    = (const float*)d_in[4]; // [128, 1024]
    float* out = (float*)d_out;

    float* zptr = nullptr;
    cudaGetSymbolAddress((void**)&zptr, g_z);

    float* s0 = out + SOFF0;
    float* s1 = out + SOFF1;
    float* r0 = out + ROFF0;
    float* r1 = out + ROFF1;
    float* v0 = out + VOFF0;
    float* v1 = out + VOFF1;

    init_counts_kernel<<<1, 1>>>();

    // Layer 1 synapse: z = W1 @ spike  (M=1024, K=512, N=256, B=32)
    gemm_bt_kernel<128, 128, 8, 8, 8>
        <<<dim3(T_LEN / 128, HID / 128, BATCH), 256>>>(W1, spike, zptr, HID, F_IN, T_LEN);

    // Layer 1 LIF
    lif_kernel<<<N_CHAINS / 256, 256>>>(v0, s0, 0);

    // Layer 2 synapse: z = W2 @ s0 (M=1024, K=1024, N=256)
    gemm_bt_kernel<128, 128, 8, 8, 8>
        <<<dim3(T_LEN / 128, HID / 128, BATCH), 256>>>(W2, s0, zptr, HID, HID, T_LEN);

    // Readout 1: r0 = R1 @ s0 (M=128, K=1024, N=256)
    gemm_bt_kernel<64, 64, 8, 4, 4>
        <<<dim3(T_LEN / 64, OUTD / 64, BATCH), 256>>>(R1, s0, r0, OUTD, HID, T_LEN);

    // Layer 2 LIF
    lif_kernel<<<N_CHAINS / 256, 256>>>(v1, s1, 1);

    // Readout 2: r1 = R2 @ s1
    gemm_bt_kernel<64, 64, 8, 4, 4>
        <<<dim3(T_LEN / 64, OUTD / 64, BATCH), 256>>>(R2, s1, r1, OUTD, HID, T_LEN);

    finalize_counts_kernel<<<1, 1>>>(out + CNTOFF);
}

// round 2
// speedup vs baseline: 1.2535x; 1.2535x over previous
#include <cuda_runtime.h>
#include <cstdint>

// Problem dims (fixed by the dataset)
#define BATCH 32
#define F_IN  512
#define T_LEN 256
#define HID   1024
#define OUTD  128

#define N_CHAINS (BATCH * HID)                  // 32768 LIF chains per layer
#define Z_ELEMS  ((size_t)BATCH * HID * T_LEN)  // 8388608

// Output layout (floats): spikes0, spikes1, readouts0, readouts1, voltages0, voltages1, counts[2]
#define SOFF0 ((size_t)0)
#define SOFF1 ((size_t)8388608)
#define ROFF0 ((size_t)16777216)
#define ROFF1 ((size_t)17825792)
#define VOFF0 ((size_t)18874368)
#define VOFF1 ((size_t)27262976)
#define CNTOFF ((size_t)35651584)

// Scratch: synaptic current z for the active layer (reused between layers)
__device__ float g_z[Z_ELEMS];
__device__ unsigned long long g_cnt[2];

__global__ void init_counts_kernel() {
    g_cnt[0] = 0ull;
    g_cnt[1] = 0ull;
}

// Y[b, m, n] = sum_k A[m,k] * X[b,k,n]
// A: [M,K] row-major (weight, shared across batch)
// X: [B,K,N] with n contiguous; Y: [B,M,N] with n contiguous.
// Register-staged double-buffered pipeline, BK=16, float4 everywhere.
template<int BM, int BN, int BK, int TM, int TN>
__global__ __launch_bounds__((BM/TM)*(BN/TN))
void gemm_pipe_kernel(const float* __restrict__ A,
                      const float* __restrict__ X,
                      float* __restrict__ Y,
                      int M, int K, int N)
{
    constexpr int THREADS = (BM / TM) * (BN / TN);
    constexpr int LA = (BM * BK) / (4 * THREADS);   // float4 A loads per thread
    constexpr int LB = (BK * BN) / (4 * THREADS);   // float4 B loads per thread
    static_assert(LA >= 1 && LB >= 1, "tile too small");

    __shared__ __align__(16) float As[2][BK][BM];
    __shared__ __align__(16) float Bs[2][BK][BN];

    const int b  = blockIdx.z;
    const int m0 = blockIdx.y * BM;
    const int n0 = blockIdx.x * BN;
    const float* __restrict__ Xb = X + (size_t)b * K * N;
    float* __restrict__ Yb = Y + (size_t)b * M * N;

    const int tid  = threadIdx.x;
    const int tcol = tid % (BN / TN);   // along N
    const int trow = tid / (BN / TN);   // along M

    float4 ra[LA], rb[LB];

    float acc[TM][TN];
#pragma unroll
    for (int i = 0; i < TM; i++)
#pragma unroll
        for (int j = 0; j < TN; j++)
            acc[i][j] = 0.0f;

    // ---- prologue: load tile 0 ----
#pragma unroll
    for (int u = 0; u < LA; u++) {
        int i  = tid + u * THREADS;
        int m  = i / (BK / 4);
        int kq = i % (BK / 4);
        ra[u] = *(const float4*)&A[(size_t)(m0 + m) * K + kq * 4];
    }
#pragma unroll
    for (int u = 0; u < LB; u++) {
        int i  = tid + u * THREADS;
        int k  = i / (BN / 4);
        int nq = i % (BN / 4);
        rb[u] = *(const float4*)&Xb[(size_t)k * N + n0 + nq * 4];
    }
#pragma unroll
    for (int u = 0; u < LA; u++) {
        int i  = tid + u * THREADS;
        int m  = i / (BK / 4);
        int kq = i % (BK / 4);
        As[0][kq * 4 + 0][m] = ra[u].x;
        As[0][kq * 4 + 1][m] = ra[u].y;
        As[0][kq * 4 + 2][m] = ra[u].z;
        As[0][kq * 4 + 3][m] = ra[u].w;
    }
#pragma unroll
    for (int u = 0; u < LB; u++) {
        int i  = tid + u * THREADS;
        int k  = i / (BN / 4);
        int nq = i % (BN / 4);
        *(float4*)&Bs[0][k][nq * 4] = rb[u];
    }
    __syncthreads();

    const int NK = K / BK;
    for (int it = 0; it < NK; it++) {
        const int cur = it & 1;
        // load next tile into registers (overlaps with compute below)
        if (it + 1 < NK) {
            const int k0n = (it + 1) * BK;
#pragma unroll
            for (int u = 0; u < LA; u++) {
                int i  = tid + u * THREADS;
                int m  = i / (BK / 4);
                int kq = i % (BK / 4);
                ra[u] = *(const float4*)&A[(size_t)(m0 + m) * K + k0n + kq * 4];
            }
#pragma unroll
            for (int u = 0; u < LB; u++) {
                int i  = tid + u * THREADS;
                int k  = i / (BN / 4);
                int nq = i % (BN / 4);
                rb[u] = *(const float4*)&Xb[(size_t)(k0n + k) * N + n0 + nq * 4];
            }
        }

        // compute on current buffer
#pragma unroll
        for (int kk = 0; kk < BK; kk++) {
            float av[TM], bv[TN];
#pragma unroll
            for (int i = 0; i < TM; i++) av[i] = As[cur][kk][trow * TM + i];
#pragma unroll
            for (int j = 0; j < TN; j++) bv[j] = Bs[cur][kk][tcol * TN + j];
#pragma unroll
            for (int i = 0; i < TM; i++)
#pragma unroll
                for (int j = 0; j < TN; j++)
                    acc[i][j] += av[i] * bv[j];
        }

        // stage next tile into the other buffer
        if (it + 1 < NK) {
            const int nxt = (it + 1) & 1;
#pragma unroll
            for (int u = 0; u < LA; u++) {
                int i  = tid + u * THREADS;
                int m  = i / (BK / 4);
                int kq = i % (BK / 4);
                As[nxt][kq * 4 + 0][m] = ra[u].x;
                As[nxt][kq * 4 + 1][m] = ra[u].y;
                As[nxt][kq * 4 + 2][m] = ra[u].z;
                As[nxt][kq * 4 + 3][m] = ra[u].w;
            }
#pragma unroll
            for (int u = 0; u < LB; u++) {
                int i  = tid + u * THREADS;
                int k  = i / (BN / 4);
                int nq = i % (BN / 4);
                *(float4*)&Bs[nxt][k][nq * 4] = rb[u];
            }
            __syncthreads();
        }
    }

#pragma unroll
    for (int i = 0; i < TM; i++) {
        const size_t row = (size_t)(m0 + trow * TM + i) * N + n0 + tcol * TN;
#pragma unroll
        for (int j = 0; j < TN; j += 4) {
            float4 v = make_float4(acc[i][j], acc[i][j + 1], acc[i][j + 2], acc[i][j + 3]);
            *(float4*)&Yb[row + j] = v;
        }
    }
}

// CUBA LIF recurrence over trailing time axis. One thread per (b, h) chain.
// cur[t]  = 0.75 * cur[t-1] + z[t]
// volt[t] = 0.97 * volt[t-1] + cur[t]   (store pre-reset)
// spike   = volt >= 1.25 ; hard reset volt -> 0 on spike
__global__ __launch_bounds__(256)
void lif_kernel(float* __restrict__ v_out,
                float* __restrict__ s_out,
                int layer)
{
    const int idx = blockIdx.x * blockDim.x + threadIdx.x; // 0 .. N_CHAINS-1 (exact)
    const float4* __restrict__ zp4 = (const float4*)(g_z + (size_t)idx * T_LEN);
    float4* __restrict__ vp4 = (float4*)(v_out + (size_t)idx * T_LEN);
    float4* __restrict__ sp4 = (float4*)(s_out + (size_t)idx * T_LEN);

    float cur = 0.0f, volt = 0.0f;
    unsigned cnt = 0;

#pragma unroll 4
    for (int t4 = 0; t4 < T_LEN / 4; t4++) {
        const float4 z = zp4[t4];
        float4 v, s;
        // step 0
        cur = 0.75f * cur + z.x;  volt = 0.97f * volt + cur;  v.x = volt;
        { bool sp = volt >= 1.25f; s.x = sp ? 1.0f : 0.0f; cnt += (unsigned)sp; if (sp) volt = 0.0f; }
        // step 1
        cur = 0.75f * cur + z.y;  volt = 0.97f * volt + cur;  v.y = volt;
        { bool sp = volt >= 1.25f; s.y = sp ? 1.0f : 0.0f; cnt += (unsigned)sp; if (sp) volt = 0.0f; }
        // step 2
        cur = 0.75f * cur + z.z;  volt = 0.97f * volt + cur;  v.z = volt;
        { bool sp = volt >= 1.25f; s.z = sp ? 1.0f : 0.0f; cnt += (unsigned)sp; if (sp) volt = 0.0f; }
        // step 3
        cur = 0.75f * cur + z.w;  volt = 0.97f * volt + cur;  v.w = volt;
        { bool sp = volt >= 1.25f; s.w = sp ? 1.0f : 0.0f; cnt += (unsigned)sp; if (sp) volt = 0.0f; }
        vp4[t4] = v;
        sp4[t4] = s;
    }

    // Deterministic integer reduction: block-level, then one atomic per block.
    __shared__ unsigned red[256];
    red[threadIdx.x] = cnt;
    __syncthreads();
#pragma unroll
    for (int off = 128; off > 0; off >>= 1) {
        if (threadIdx.x < off) red[threadIdx.x] += red[threadIdx.x + off];
        __syncthreads();
    }
    if (threadIdx.x == 0)
        atomicAdd(&g_cnt[layer], (unsigned long long)red[0]);
}

__global__ void finalize_counts_kernel(float* __restrict__ out)
{
    const double total = (double)((size_t)BATCH * HID * T_LEN);
    out[0] = (float)((double)g_cnt[0] / total);
    out[1] = (float)((double)g_cnt[1] / total);
}

extern "C" void kernel_launch(void* const* d_in, const int* in_sizes, int n_in,
                              void* d_out, int out_size)
{
    const float* spike = (const float*)d_in[0]; // [32, 512, 256]
    const float* W1    = (const float*)d_in[1]; // [1024, 512]
    const float* W2    = (const float*)d_in[2]; // [1024, 1024]
    const float* R1    = (const float*)d_in[3]; // [128, 1024]
    const float* R2    = (const float*)d_in[4]; // [128, 1024]
    float* out = (float*)d_out;

    float* zptr = nullptr;
    cudaGetSymbolAddress((void**)&zptr, g_z);

    float* s0 = out + SOFF0;
    float* s1 = out + SOFF1;
    float* r0 = out + ROFF0;
    float* r1 = out + ROFF1;
    float* v0 = out + VOFF0;
    float* v1 = out + VOFF1;

    init_counts_kernel<<<1, 1>>>();

    // Layer 1 synapse: z = W1 @ spike  (M=1024, K=512, N=256, B=32)
    gemm_pipe_kernel<128, 128, 16, 8, 8>
        <<<dim3(T_LEN / 128, HID / 128, BATCH), 256>>>(W1, spike, zptr, HID, F_IN, T_LEN);

    // Layer 1 LIF
    lif_kernel<<<N_CHAINS / 256, 256>>>(v0, s0, 0);

    // Layer 2 synapse: z = W2 @ s0 (M=1024, K=1024, N=256)
    gemm_pipe_kernel<128, 128, 16, 8, 8>
        <<<dim3(T_LEN / 128, HID / 128, BATCH), 256>>>(W2, s0, zptr, HID, HID, T_LEN);

    // Readout 1: r0 = R1 @ s0 (M=128, K=1024, N=256)
    gemm_pipe_kernel<64, 64, 16, 4, 4>
        <<<dim3(T_LEN / 64, OUTD / 64, BATCH), 256>>>(R1, s0, r0, OUTD, HID, T_LEN);

    // Layer 2 LIF
    lif_kernel<<<N_CHAINS / 256, 256>>>(v1, s1, 1);

    // Readout 2: r1 = R2 @ s1
    gemm_pipe_kernel<64, 64, 16, 4, 4>
        <<<dim3(T_LEN / 64, OUTD / 64, BATCH), 256>>>(R2, s1, r1, OUTD, HID, T_LEN);

    finalize_counts_kernel<<<1, 1>>>(out + CNTOFF);
}